// round 6
// baseline (speedup 1.0000x reference)
#include <cuda_runtime.h>
#include <math.h>

#define BB   64
#define SS   2048
#define DD   1024
#define HH   300
#define OO   2
#define SCH  16                 // s-chunks for the big reduction
#define SPC  (SS / SCH)         // 128 s per chunk
#define D4   (DD / 4)           // 256 float4 per row

// Scratch (allocation-free rule: __device__ globals)
__device__ int   g_end[BB];
__device__ float g_partial[BB][SCH][DD];

// ---------------------------------------------------------------------------
// 1) first index where input_ids[b,s]==1; fallback = B (reference's
//    except-path quirk). Separate tiny launch — fusing it into the bandwidth
//    kernel regressed 15us in R4.
// ---------------------------------------------------------------------------
__global__ void k_end(const int* __restrict__ ids) {
    int b = blockIdx.x;
    __shared__ int m;
    if (threadIdx.x == 0) m = 0x7fffffff;
    __syncthreads();
    const int* row = ids + b * SS;
    for (int s = threadIdx.x; s < SS; s += blockDim.x)
        if (row[s] == 1) atomicMin(&m, s);
    __syncthreads();
    if (threadIdx.x == 0) g_end[b] = (m == 0x7fffffff) ? BB : m;
}

// ---------------------------------------------------------------------------
// 2) big masked segment-sum with COMPACTED row list (proved ~8us win in R5):
//    stage (s, m) pairs with m!=0 && s<end into smem, then run an
//    unconditional 4-way-unrolled float4 stream. ~at DRAM/LTS cap.
// ---------------------------------------------------------------------------
__global__ __launch_bounds__(256) void k_reduce(const float* __restrict__ x,
                                                const float* __restrict__ mask) {
    int b = blockIdx.x;
    int c = blockIdx.y;
    int t = threadIdx.x;
    int end = g_end[b];
    int s0  = c * SPC;

    __shared__ float s_m[SPC];
    __shared__ int   s_idx[SPC];
    __shared__ int   s_cnt;
    if (t == 0) s_cnt = 0;
    __syncthreads();

    if (t < SPC) {                          // first 128 threads stage+compact
        int s = s0 + t;
        float m = (s < end) ? mask[b * SS + s] : 0.0f;
        if (m != 0.0f) {
            int p = atomicAdd(&s_cnt, 1);
            s_idx[p] = t;
            s_m[p]   = m;
        }
    }
    __syncthreads();
    int n = s_cnt;

    const float4* xp = (const float4*)(x + (long long)b * SS * DD)
                       + (long long)s0 * D4 + t;

    float4 acc = make_float4(0.f, 0.f, 0.f, 0.f);
    int i = 0;
    for (; i + 4 <= n; i += 4) {
        int   j0 = s_idx[i],     j1 = s_idx[i + 1];
        int   j2 = s_idx[i + 2], j3 = s_idx[i + 3];
        float m0 = s_m[i],       m1 = s_m[i + 1];
        float m2 = s_m[i + 2],   m3 = s_m[i + 3];
        float4 v0 = xp[j0 * D4];
        float4 v1 = xp[j1 * D4];
        float4 v2 = xp[j2 * D4];
        float4 v3 = xp[j3 * D4];
        acc.x += v0.x * m0; acc.y += v0.y * m0; acc.z += v0.z * m0; acc.w += v0.w * m0;
        acc.x += v1.x * m1; acc.y += v1.y * m1; acc.z += v1.z * m1; acc.w += v1.w * m1;
        acc.x += v2.x * m2; acc.y += v2.y * m2; acc.z += v2.z * m2; acc.w += v2.w * m2;
        acc.x += v3.x * m3; acc.y += v3.y * m3; acc.z += v3.z * m3; acc.w += v3.w * m3;
    }
    for (; i < n; i++) {
        int   j = s_idx[i];
        float m = s_m[i];
        float4 v = xp[j * D4];
        acc.x += v.x * m; acc.y += v.y * m; acc.z += v.z * m; acc.w += v.w * m;
    }
    ((float4*)g_partial[b][c])[t] = acc;
}

// ---------------------------------------------------------------------------
// 3) FUSED TAIL: combine + hidden + out in one launch, one block per batch.
//    512 threads = 16 warps.
//    a) fold 16 partials -> euph[1024] in smem (partials are L2-resident)
//    b) warp-per-h GEMV: hidden[300] = tanh(euph @ W1^T + b1)
//    c) 2 warps: out[2] = hidden @ W2^T + b2
// ---------------------------------------------------------------------------
__global__ __launch_bounds__(512) void k_tail(const float* __restrict__ W1,
                                              const float* __restrict__ b1,
                                              const float* __restrict__ W2,
                                              const float* __restrict__ b2,
                                              float* __restrict__ out) {
    int b    = blockIdx.x;
    int t    = threadIdx.x;
    int warp = t >> 5;
    int lane = t & 31;

    __shared__ float se[DD];       // euph
    __shared__ float sh[HH];       // hidden

    // a) fold partials + divide by end (threads 0..255, one float4 each)
    if (t < D4) {
        float4 acc = make_float4(0.f, 0.f, 0.f, 0.f);
#pragma unroll
        for (int c = 0; c < SCH; c++) {
            float4 v = ((const float4*)g_partial[b][c])[t];
            acc.x += v.x; acc.y += v.y; acc.z += v.z; acc.w += v.w;
        }
        float inv = 1.0f / (float)g_end[b];
        acc.x *= inv; acc.y *= inv; acc.z *= inv; acc.w *= inv;
        ((float4*)se)[t] = acc;
    }
    __syncthreads();

    // b) hidden: 16 warps stride over the 300 h rows
    const float4* e4 = (const float4*)se;
    for (int h = warp; h < HH; h += 16) {
        const float4* w4 = (const float4*)(W1 + (long long)h * DD);
        float s = 0.f;
#pragma unroll
        for (int i = 0; i < 8; i++) {
            float4 w = w4[lane + 32 * i];
            float4 e = e4[lane + 32 * i];
            s += e.x * w.x + e.y * w.y + e.z * w.z + e.w * w.w;
        }
#pragma unroll
        for (int off = 16; off > 0; off >>= 1)
            s += __shfl_xor_sync(0xffffffffu, s, off);
        if (lane == 0)
            sh[h] = tanhf(s + b1[h]);
    }
    __syncthreads();

    // c) out: warps 0 and 1, one output each
    if (warp < OO) {
        const float* w = W2 + warp * HH;
        float s = 0.f;
#pragma unroll 5
        for (int k = lane; k < HH; k += 32)
            s += sh[k] * w[k];
#pragma unroll
        for (int off = 16; off > 0; off >>= 1)
            s += __shfl_xor_sync(0xffffffffu, s, off);
        if (lane == 0)
            out[b * OO + warp] = s + b2[warp];
    }
}

// ---------------------------------------------------------------------------
extern "C" void kernel_launch(void* const* d_in, const int* in_sizes, int n_in,
                              void* d_out, int out_size) {
    const float* x    = (const float*)d_in[0];       // [B,S,D] f32
    const int*   ids  = (const int*)d_in[1];         // [B,S]   i32 (JAX x64 off)
    const float* mask = (const float*)d_in[2];       // [B,S,1] f32
    const float* W1   = (const float*)d_in[3];       // [H,D]
    const float* b1   = (const float*)d_in[4];       // [H]
    const float* W2   = (const float*)d_in[5];       // [OUT,H]
    const float* b2   = (const float*)d_in[6];       // [OUT]
    float*       out  = (float*)d_out;               // [B,OUT]

    k_end   <<<BB, 256>>>(ids);
    k_reduce<<<dim3(BB, SCH), 256>>>(x, mask);
    k_tail  <<<BB, 512>>>(W1, b1, W2, b2, out);
}

// round 7
// speedup vs baseline: 1.3853x; 1.3853x over previous
#include <cuda_runtime.h>
#include <math.h>

#define BB   64
#define SS   2048
#define DD   1024
#define HH   300
#define OO   2
#define SCH  16                 // s-chunks for the big reduction
#define SPC  (SS / SCH)         // 128 s per chunk
#define D4   (DD / 4)           // 256 float4 per row

// Scratch (allocation-free rule: __device__ globals)
__device__ int   g_end[BB];
__device__ float g_partial[BB][SCH][DD];
__device__ float g_euph[BB][DD];
__device__ float g_hidden[BB][HH];

// ---------------------------------------------------------------------------
// 1) first index where input_ids[b,s]==1; fallback = B (reference's
//    except-path quirk). 1024 threads, int2 loads: one memory round-trip.
// ---------------------------------------------------------------------------
__global__ __launch_bounds__(1024) void k_end(const int* __restrict__ ids) {
    int b = blockIdx.x;
    int t = threadIdx.x;
    __shared__ int m;
    if (t == 0) m = 0x7fffffff;
    __syncthreads();
    const int2* row = (const int2*)(ids + b * SS);
    int2 v = row[t];                       // 1024 threads * 2 ids = 2048
    if (v.x == 1) atomicMin(&m, 2 * t);
    if (v.y == 1) atomicMin(&m, 2 * t + 1);
    __syncthreads();
    if (t == 0) g_end[b] = (m == 0x7fffffff) ? BB : m;
}

// ---------------------------------------------------------------------------
// 2) big masked segment-sum with COMPACTED row list (R5 win, ~at DRAM cap):
//    stage (s, m) pairs with m!=0 && s<end into smem, then run an
//    unconditional 4-way-unrolled float4 stream.
// ---------------------------------------------------------------------------
__global__ __launch_bounds__(256) void k_reduce(const float* __restrict__ x,
                                                const float* __restrict__ mask) {
    int b = blockIdx.x;
    int c = blockIdx.y;
    int t = threadIdx.x;
    int end = g_end[b];
    int s0  = c * SPC;

    __shared__ float s_m[SPC];
    __shared__ int   s_idx[SPC];
    __shared__ int   s_cnt;
    if (t == 0) s_cnt = 0;
    __syncthreads();

    if (t < SPC) {                          // first 128 threads stage+compact
        int s = s0 + t;
        float m = (s < end) ? mask[b * SS + s] : 0.0f;
        if (m != 0.0f) {
            int p = atomicAdd(&s_cnt, 1);
            s_idx[p] = t;
            s_m[p]   = m;
        }
    }
    __syncthreads();
    int n = s_cnt;

    const float4* xp = (const float4*)(x + (long long)b * SS * DD)
                       + (long long)s0 * D4 + t;

    float4 acc = make_float4(0.f, 0.f, 0.f, 0.f);
    int i = 0;
    for (; i + 4 <= n; i += 4) {
        int   j0 = s_idx[i],     j1 = s_idx[i + 1];
        int   j2 = s_idx[i + 2], j3 = s_idx[i + 3];
        float m0 = s_m[i],       m1 = s_m[i + 1];
        float m2 = s_m[i + 2],   m3 = s_m[i + 3];
        float4 v0 = xp[j0 * D4];
        float4 v1 = xp[j1 * D4];
        float4 v2 = xp[j2 * D4];
        float4 v3 = xp[j3 * D4];
        acc.x += v0.x * m0; acc.y += v0.y * m0; acc.z += v0.z * m0; acc.w += v0.w * m0;
        acc.x += v1.x * m1; acc.y += v1.y * m1; acc.z += v1.z * m1; acc.w += v1.w * m1;
        acc.x += v2.x * m2; acc.y += v2.y * m2; acc.z += v2.z * m2; acc.w += v2.w * m2;
        acc.x += v3.x * m3; acc.y += v3.y * m3; acc.z += v3.z * m3; acc.w += v3.w * m3;
    }
    for (; i < n; i++) {
        int   j = s_idx[i];
        float m = s_m[i];
        float4 v = xp[j * D4];
        acc.x += v.x * m; acc.y += v.y * m; acc.z += v.z * m; acc.w += v.w * m;
    }
    ((float4*)g_partial[b][c])[t] = acc;
}

// ---------------------------------------------------------------------------
// 3) fold the SCH partials and divide by end. Grid (64 b, 4 q) = 256 blocks
//    (wider than the old 64 -> less latency-floor). Thread t owns one float.
// ---------------------------------------------------------------------------
__global__ __launch_bounds__(256) void k_combine() {
    int b = blockIdx.x;
    int d = blockIdx.y * 256 + threadIdx.x;
    float inv = 1.0f / (float)g_end[b];
    float acc = 0.f;
#pragma unroll
    for (int c = 0; c < SCH; c++)
        acc += g_partial[b][c][d];
    g_euph[b][d] = acc * inv;
}

// ---------------------------------------------------------------------------
// 4) hidden = tanh(euph @ W1^T + b1).  Grid (16 bTiles, 75 hGroups) = 1200
//    blocks (parallelism is what these L2-resident GEMVs need: 4800blk=12us,
//    300blk=20us, 64blk=50us measured). Warp owns one h, W1 row in regs,
//    reused across 4 batches -> ~38MB L2 vs 77MB for the no-reuse version.
// ---------------------------------------------------------------------------
__global__ __launch_bounds__(128) void k_hidden(const float* __restrict__ W1,
                                                const float* __restrict__ b1) {
    int warp = threadIdx.x >> 5;
    int lane = threadIdx.x & 31;
    int h    = blockIdx.y * 4 + warp;          // 75*4 = 300, always valid
    int b0   = blockIdx.x * 4;                 // 16*4  = 64

    const float4* w4p = (const float4*)(W1 + (long long)h * DD);
    float4 w[8];
#pragma unroll
    for (int i = 0; i < 8; i++) w[i] = w4p[lane + 32 * i];
    float bias = b1[h];

#pragma unroll
    for (int bi = 0; bi < 4; bi++) {
        const float4* e4 = (const float4*)g_euph[b0 + bi];
        float s = 0.f;
#pragma unroll
        for (int i = 0; i < 8; i++) {
            float4 e = e4[lane + 32 * i];
            s += e.x * w[i].x + e.y * w[i].y + e.z * w[i].z + e.w * w[i].w;
        }
#pragma unroll
        for (int off = 16; off > 0; off >>= 1)
            s += __shfl_xor_sync(0xffffffffu, s, off);
        if (lane == 0)
            g_hidden[b0 + bi][h] = tanhf(s + bias);
    }
}

// ---------------------------------------------------------------------------
// 5) out = hidden @ W2^T + b2.  Warp per (b, o): 128 warps over 8 blocks
//    (old: 64 blocks x 64thr, occ 3.2%, 10.9us latency floor).
// ---------------------------------------------------------------------------
__global__ __launch_bounds__(512) void k_out(const float* __restrict__ W2,
                                             const float* __restrict__ b2,
                                             float* __restrict__ out) {
    int gw   = blockIdx.x * 16 + (threadIdx.x >> 5);   // 0..127
    int lane = threadIdx.x & 31;
    int b    = gw >> 1;
    int o    = gw & 1;

    const float* hid = g_hidden[b];
    const float* w   = W2 + o * HH;
    float s = 0.f;
#pragma unroll 5
    for (int k = lane; k < HH; k += 32)
        s += hid[k] * w[k];
#pragma unroll
    for (int off = 16; off > 0; off >>= 1)
        s += __shfl_xor_sync(0xffffffffu, s, off);
    if (lane == 0)
        out[b * OO + o] = s + b2[o];
}

// ---------------------------------------------------------------------------
extern "C" void kernel_launch(void* const* d_in, const int* in_sizes, int n_in,
                              void* d_out, int out_size) {
    const float* x    = (const float*)d_in[0];       // [B,S,D] f32
    const int*   ids  = (const int*)d_in[1];         // [B,S]   i32 (JAX x64 off)
    const float* mask = (const float*)d_in[2];       // [B,S,1] f32
    const float* W1   = (const float*)d_in[3];       // [H,D]
    const float* b1   = (const float*)d_in[4];       // [H]
    const float* W2   = (const float*)d_in[5];       // [OUT,H]
    const float* b2   = (const float*)d_in[6];       // [OUT]
    float*       out  = (float*)d_out;               // [B,OUT]

    k_end    <<<BB, 1024>>>(ids);
    k_reduce <<<dim3(BB, SCH), 256>>>(x, mask);
    k_combine<<<dim3(BB, 4), 256>>>();
    k_hidden <<<dim3(16, HH / 4), 128>>>(W1, b1);
    k_out    <<<8, 512>>>(W2, b2, out);
}